// round 1
// baseline (speedup 1.0000x reference)
#include <cuda_runtime.h>
#include <math.h>

#define TT   60
#define HID  32
#define NG   128      // 4*HID gates
#define EPSF 1e-5f

// scratch: per-frame input-projection of the gates (w_ih @ fln + b_ih + b_hh)
__device__ float g_ihp[TT * NG];

__device__ __forceinline__ float sigm(float x) { return 1.0f / (1.0f + expf(-x)); }

// ---------------------------------------------------------------------------
// Kernel A: one block per frame t. Computes
//   f1 = relu(w00 @ x_t + b00)            [63]
//   f2 = relu(w01 @ f1 + b01)             [64]
//   fln = LayerNorm(f2) * ln_g + ln_b     [64]
//   g_ihp[t] = w_ih @ fln + b_ih + b_hh   [128]
// ---------------------------------------------------------------------------
__global__ void __launch_bounds__(128, 1) frame_kernel(
    const float* __restrict__ x,
    const float* __restrict__ w00, const float* __restrict__ b00,
    const float* __restrict__ w01, const float* __restrict__ b01,
    const float* __restrict__ ln_g, const float* __restrict__ ln_b,
    const float* __restrict__ w_ih, const float* __restrict__ b_ih,
    const float* __restrict__ b_hh)
{
    __shared__ float xs[63];
    __shared__ float f1s[63];
    __shared__ float f2s[64];
    __shared__ float flns[64];
    __shared__ float mu_s, rstd_s;

    const int t   = blockIdx.x;
    const int tid = threadIdx.x;

    if (tid < 63) xs[tid] = x[t * 63 + tid];
    __syncthreads();

    // f1 = relu(w00 @ xs + b00), 63 outputs, dot length 63
    if (tid < 63) {
        const float* wr = w00 + tid * 63;
        float a0 = 0.f, a1 = 0.f, a2 = 0.f, a3 = 0.f;
        #pragma unroll
        for (int k = 0; k < 60; k += 4) {
            a0 += wr[k + 0] * xs[k + 0];
            a1 += wr[k + 1] * xs[k + 1];
            a2 += wr[k + 2] * xs[k + 2];
            a3 += wr[k + 3] * xs[k + 3];
        }
        a0 += wr[60] * xs[60];
        a1 += wr[61] * xs[61];
        a2 += wr[62] * xs[62];
        float v = a0 + a1 + a2 + a3 + b00[tid];
        f1s[tid] = fmaxf(v, 0.0f);
    }
    __syncthreads();

    // f2 = relu(w01 @ f1 + b01), 64 outputs, dot length 63
    if (tid < 64) {
        const float* wr = w01 + tid * 63;
        float a0 = 0.f, a1 = 0.f, a2 = 0.f, a3 = 0.f;
        #pragma unroll
        for (int k = 0; k < 60; k += 4) {
            a0 += wr[k + 0] * f1s[k + 0];
            a1 += wr[k + 1] * f1s[k + 1];
            a2 += wr[k + 2] * f1s[k + 2];
            a3 += wr[k + 3] * f1s[k + 3];
        }
        a0 += wr[60] * f1s[60];
        a1 += wr[61] * f1s[61];
        a2 += wr[62] * f1s[62];
        float v = a0 + a1 + a2 + a3 + b01[tid];
        f2s[tid] = fmaxf(v, 0.0f);
    }
    __syncthreads();

    // LayerNorm stats over the 64 values (warp 0 reduces sum and sumsq)
    if (tid < 32) {
        float v0 = f2s[tid], v1 = f2s[tid + 32];
        float s  = v0 + v1;
        float ss = v0 * v0 + v1 * v1;
        #pragma unroll
        for (int off = 16; off > 0; off >>= 1) {
            s  += __shfl_xor_sync(0xffffffffu, s,  off);
            ss += __shfl_xor_sync(0xffffffffu, ss, off);
        }
        if (tid == 0) {
            float mu  = s * (1.0f / 64.0f);
            float var = ss * (1.0f / 64.0f) - mu * mu;
            mu_s   = mu;
            rstd_s = rsqrtf(var + EPSF);
        }
    }
    __syncthreads();

    if (tid < 64)
        flns[tid] = (f2s[tid] - mu_s) * rstd_s * ln_g[tid] + ln_b[tid];
    __syncthreads();

    // ihp[g] = w_ih[g] . fln + b_ih[g] + b_hh[g], 128 outputs, dot length 64
    {
        const float* wr = w_ih + tid * 64;
        float a0 = 0.f, a1 = 0.f, a2 = 0.f, a3 = 0.f;
        #pragma unroll
        for (int k = 0; k < 64; k += 4) {
            a0 += wr[k + 0] * flns[k + 0];
            a1 += wr[k + 1] * flns[k + 1];
            a2 += wr[k + 2] * flns[k + 2];
            a3 += wr[k + 3] * flns[k + 3];
        }
        g_ihp[t * NG + tid] = a0 + a1 + a2 + a3 + b_ih[tid] + b_hh[tid];
    }
}

// ---------------------------------------------------------------------------
// Kernel B: single block, 128 threads. The sequential LSTM recurrence:
// per step only gates = ihp[t] + w_hh @ h (w_hh rows register-resident),
// then the elementwise cell on 32 lanes. Tail MLP + BatchNorm fused after.
// ---------------------------------------------------------------------------
__global__ void __launch_bounds__(128, 1) recur_kernel(
    const float* __restrict__ w_hh,
    const float* __restrict__ bn_g, const float* __restrict__ bn_b,
    const float* __restrict__ w10, const float* __restrict__ b10,
    const float* __restrict__ w11, const float* __restrict__ b11,
    const float* __restrict__ w12, const float* __restrict__ b12,
    float* __restrict__ out)
{
    __shared__ float hs[HID];
    __shared__ float gs[NG];
    __shared__ float hbs[HID];
    __shared__ float a1s[HID];
    __shared__ float a2s[HID];

    const int tid = threadIdx.x;

    // register-resident w_hh row for this gate
    float whh[HID];
    #pragma unroll
    for (int k = 0; k < HID; k++) whh[k] = w_hh[tid * HID + k];

    float c = 0.0f;               // cell state, lanes 0..31 only
    if (tid < HID) hs[tid] = 0.0f;
    __syncthreads();

    for (int t = 0; t < TT; t++) {
        // prefetch the input projection (L2 hit, overlaps with the dot below)
        float ip = g_ihp[t * NG + tid];

        float a0 = 0.f, a1 = 0.f, a2 = 0.f, a3 = 0.f;
        #pragma unroll
        for (int k = 0; k < HID; k += 4) {
            a0 += whh[k + 0] * hs[k + 0];   // broadcast smem reads: conflict-free
            a1 += whh[k + 1] * hs[k + 1];
            a2 += whh[k + 2] * hs[k + 2];
            a3 += whh[k + 3] * hs[k + 3];
        }
        gs[tid] = ip + a0 + a1 + a2 + a3;
        __syncthreads();

        if (tid < HID) {
            float ig = gs[tid];
            float fg = gs[HID + tid];
            float gg = gs[2 * HID + tid];
            float og = gs[3 * HID + tid];
            c = sigm(fg) * c + sigm(ig) * tanhf(gg);
            hs[tid] = sigm(og) * tanhf(c);
        }
        __syncthreads();
    }

    // BatchNorm1d eval (running_mean=0, running_var=1)
    if (tid < HID)
        hbs[tid] = hs[tid] * rsqrtf(1.0f + EPSF) * bn_g[tid] + bn_b[tid];
    __syncthreads();

    if (tid < HID) {
        const float* wr = w10 + tid * HID;
        float s = 0.f;
        #pragma unroll
        for (int k = 0; k < HID; k++) s += wr[k] * hbs[k];
        a1s[tid] = fmaxf(s + b10[tid], 0.0f);
    }
    __syncthreads();

    if (tid < HID) {
        const float* wr = w11 + tid * HID;
        float s = 0.f;
        #pragma unroll
        for (int k = 0; k < HID; k++) s += wr[k] * a1s[k];
        a2s[tid] = fmaxf(s + b11[tid], 0.0f);
    }
    __syncthreads();

    #pragma unroll
    for (int o = tid; o < 256; o += 128) {
        const float* wr = w12 + o * HID;
        float s = 0.f;
        #pragma unroll
        for (int k = 0; k < HID; k++) s += wr[k] * a2s[k];
        out[o] = s + b12[o];
    }
}

// ---------------------------------------------------------------------------
// launch
// ---------------------------------------------------------------------------
extern "C" void kernel_launch(void* const* d_in, const int* in_sizes, int n_in,
                              void* d_out, int out_size)
{
    const float* x    = (const float*)d_in[0];
    const float* w00  = (const float*)d_in[1];
    const float* b00  = (const float*)d_in[2];
    const float* w01  = (const float*)d_in[3];
    const float* b01  = (const float*)d_in[4];
    const float* ln_g = (const float*)d_in[5];
    const float* ln_b = (const float*)d_in[6];
    const float* w_ih = (const float*)d_in[7];
    const float* w_hh = (const float*)d_in[8];
    const float* b_ih = (const float*)d_in[9];
    const float* b_hh = (const float*)d_in[10];
    const float* bn_g = (const float*)d_in[11];
    const float* bn_b = (const float*)d_in[12];
    const float* w10  = (const float*)d_in[13];
    const float* b10  = (const float*)d_in[14];
    const float* w11  = (const float*)d_in[15];
    const float* b11  = (const float*)d_in[16];
    const float* w12  = (const float*)d_in[17];
    const float* b12  = (const float*)d_in[18];
    float* out = (float*)d_out;

    frame_kernel<<<TT, 128>>>(x, w00, b00, w01, b01, ln_g, ln_b, w_ih, b_ih, b_hh);
    recur_kernel<<<1, 128>>>(w_hh, bn_g, bn_b, w10, b10, w11, b11, w12, b12, out);
}

// round 3
// speedup vs baseline: 1.5653x; 1.5653x over previous
#include <cuda_runtime.h>
#include <math.h>

#define TT   60
#define HID  32
#define NG   128      // 4*HID gates
#define EPSF 1e-5f

// scratch: per-frame input-projection of the gates (w_ih @ fln + b_ih + b_hh)
__device__ float g_ihp[TT * NG];

// MUFU.TANH-based fast activations (sm_75+ tanh.approx.f32, lat 16)
__device__ __forceinline__ float tanh_fast(float x) {
    float y;
    asm("tanh.approx.f32 %0, %1;" : "=f"(y) : "f"(x));
    return y;
}
__device__ __forceinline__ float sigm_fast(float x) {
    return fmaf(0.5f, tanh_fast(0.5f * x), 0.5f);
}

// ---------------------------------------------------------------------------
// Kernel A: one block per frame t. Computes
//   f1 = relu(w00 @ x_t + b00)            [63]
//   f2 = relu(w01 @ f1 + b01)             [64]
//   fln = LayerNorm(f2) * ln_g + ln_b     [64]
//   g_ihp[t] = w_ih @ fln + b_ih + b_hh   [128]
// ---------------------------------------------------------------------------
__global__ void __launch_bounds__(128, 1) frame_kernel(
    const float* __restrict__ x,
    const float* __restrict__ w00, const float* __restrict__ b00,
    const float* __restrict__ w01, const float* __restrict__ b01,
    const float* __restrict__ ln_g, const float* __restrict__ ln_b,
    const float* __restrict__ w_ih, const float* __restrict__ b_ih,
    const float* __restrict__ b_hh)
{
    __shared__ float xs[63];
    __shared__ float f1s[63];
    __shared__ float f2s[64];
    __shared__ float flns[64];
    __shared__ float mu_s, rstd_s;

    const int t   = blockIdx.x;
    const int tid = threadIdx.x;

    if (tid < 63) xs[tid] = x[t * 63 + tid];
    __syncthreads();

    // f1 = relu(w00 @ xs + b00), 63 outputs, dot length 63
    if (tid < 63) {
        const float* wr = w00 + tid * 63;
        float a0 = 0.f, a1 = 0.f, a2 = 0.f, a3 = 0.f;
        #pragma unroll
        for (int k = 0; k < 60; k += 4) {
            a0 += wr[k + 0] * xs[k + 0];
            a1 += wr[k + 1] * xs[k + 1];
            a2 += wr[k + 2] * xs[k + 2];
            a3 += wr[k + 3] * xs[k + 3];
        }
        a0 += wr[60] * xs[60];
        a1 += wr[61] * xs[61];
        a2 += wr[62] * xs[62];
        float v = a0 + a1 + a2 + a3 + b00[tid];
        f1s[tid] = fmaxf(v, 0.0f);
    }
    __syncthreads();

    // f2 = relu(w01 @ f1 + b01), 64 outputs, dot length 63
    if (tid < 64) {
        const float* wr = w01 + tid * 63;
        float a0 = 0.f, a1 = 0.f, a2 = 0.f, a3 = 0.f;
        #pragma unroll
        for (int k = 0; k < 60; k += 4) {
            a0 += wr[k + 0] * f1s[k + 0];
            a1 += wr[k + 1] * f1s[k + 1];
            a2 += wr[k + 2] * f1s[k + 2];
            a3 += wr[k + 3] * f1s[k + 3];
        }
        a0 += wr[60] * f1s[60];
        a1 += wr[61] * f1s[61];
        a2 += wr[62] * f1s[62];
        float v = a0 + a1 + a2 + a3 + b01[tid];
        f2s[tid] = fmaxf(v, 0.0f);
    }
    __syncthreads();

    // LayerNorm stats over the 64 values (warp 0 reduces sum and sumsq)
    if (tid < 32) {
        float v0 = f2s[tid], v1 = f2s[tid + 32];
        float s  = v0 + v1;
        float ss = v0 * v0 + v1 * v1;
        #pragma unroll
        for (int off = 16; off > 0; off >>= 1) {
            s  += __shfl_xor_sync(0xffffffffu, s,  off);
            ss += __shfl_xor_sync(0xffffffffu, ss, off);
        }
        if (tid == 0) {
            float mu  = s * (1.0f / 64.0f);
            float var = ss * (1.0f / 64.0f) - mu * mu;
            mu_s   = mu;
            rstd_s = rsqrtf(var + EPSF);
        }
    }
    __syncthreads();

    if (tid < 64)
        flns[tid] = (f2s[tid] - mu_s) * rstd_s * ln_g[tid] + ln_b[tid];
    __syncthreads();

    // ihp[g] = w_ih[g] . fln + b_ih[g] + b_hh[g], 128 outputs, dot length 64
    {
        const float* wr = w_ih + tid * 64;
        float a0 = 0.f, a1 = 0.f, a2 = 0.f, a3 = 0.f;
        #pragma unroll
        for (int k = 0; k < 64; k += 4) {
            a0 += wr[k + 0] * flns[k + 0];
            a1 += wr[k + 1] * flns[k + 1];
            a2 += wr[k + 2] * flns[k + 2];
            a3 += wr[k + 3] * flns[k + 3];
        }
        g_ihp[t * NG + tid] = a0 + a1 + a2 + a3 + b_ih[tid] + b_hh[tid];
    }
}

// ---------------------------------------------------------------------------
// Kernel B: single block, 128 threads.
//  - stage all T*128 input projections into SMEM once (kills per-step L2 latency)
//  - per step: gates = ihp_smem[t] + w_hh @ h  (w_hh register-resident,
//    h read via LDS.128 broadcast), then MUFU.TANH-based cell update
// ---------------------------------------------------------------------------
__global__ void __launch_bounds__(128, 1) recur_kernel(
    const float* __restrict__ w_hh,
    const float* __restrict__ bn_g, const float* __restrict__ bn_b,
    const float* __restrict__ w10, const float* __restrict__ b10,
    const float* __restrict__ w11, const float* __restrict__ b11,
    const float* __restrict__ w12, const float* __restrict__ b12,
    float* __restrict__ out)
{
    __shared__ float ihps[TT * NG];          // 30 KB
    __shared__ __align__(16) float hs[HID];
    __shared__ float gs[NG];
    __shared__ float hbs[HID];
    __shared__ float a1s[HID];
    __shared__ float a2s[HID];

    const int tid = threadIdx.x;

    // register-resident w_hh row for this thread's gate
    float whh[HID];
    #pragma unroll
    for (int k = 0; k < HID; k++) whh[k] = w_hh[tid * HID + k];

    // stage all input projections into SMEM (coalesced: 128 threads x 60 rows)
    #pragma unroll
    for (int t = 0; t < TT; t++)
        ihps[t * NG + tid] = g_ihp[t * NG + tid];

    float c = 0.0f;               // cell state, lanes 0..31 only
    if (tid < HID) hs[tid] = 0.0f;
    __syncthreads();

    for (int t = 0; t < TT; t++) {
        float ip = ihps[t * NG + tid];

        float a0 = 0.f, a1 = 0.f, a2 = 0.f, a3 = 0.f;
        const float4* h4 = (const float4*)hs;
        #pragma unroll
        for (int k = 0; k < HID / 4; k++) {
            float4 hv = h4[k];
            a0 += whh[4 * k + 0] * hv.x;
            a1 += whh[4 * k + 1] * hv.y;
            a2 += whh[4 * k + 2] * hv.z;
            a3 += whh[4 * k + 3] * hv.w;
        }
        gs[tid] = ip + (a0 + a1) + (a2 + a3);
        __syncthreads();

        if (tid < HID) {
            float ig = gs[tid];
            float fg = gs[HID + tid];
            float gg = gs[2 * HID + tid];
            float og = gs[3 * HID + tid];
            c = sigm_fast(fg) * c + sigm_fast(ig) * tanh_fast(gg);
            hs[tid] = sigm_fast(og) * tanh_fast(c);
        }
        __syncthreads();
    }

    // BatchNorm1d eval (running_mean=0, running_var=1)
    if (tid < HID)
        hbs[tid] = hs[tid] * rsqrtf(1.0f + EPSF) * bn_g[tid] + bn_b[tid];
    __syncthreads();

    if (tid < HID) {
        const float* wr = w10 + tid * HID;
        float s = 0.f;
        #pragma unroll
        for (int k = 0; k < HID; k++) s += wr[k] * hbs[k];
        a1s[tid] = fmaxf(s + b10[tid], 0.0f);
    }
    __syncthreads();

    if (tid < HID) {
        const float* wr = w11 + tid * HID;
        float s = 0.f;
        #pragma unroll
        for (int k = 0; k < HID; k++) s += wr[k] * a1s[k];
        a2s[tid] = fmaxf(s + b11[tid], 0.0f);
    }
    __syncthreads();

    #pragma unroll
    for (int o = tid; o < 256; o += 128) {
        const float* wr = w12 + o * HID;
        float s = 0.f;
        #pragma unroll
        for (int k = 0; k < HID; k++) s += wr[k] * a2s[k];
        out[o] = s + b12[o];
    }
}

// ---------------------------------------------------------------------------
// launch
// ---------------------------------------------------------------------------
extern "C" void kernel_launch(void* const* d_in, const int* in_sizes, int n_in,
                              void* d_out, int out_size)
{
    const float* x    = (const float*)d_in[0];
    const float* w00  = (const float*)d_in[1];
    const float* b00  = (const float*)d_in[2];
    const float* w01  = (const float*)d_in[3];
    const float* b01  = (const float*)d_in[4];
    const float* ln_g = (const float*)d_in[5];
    const float* ln_b = (const float*)d_in[6];
    const float* w_ih = (const float*)d_in[7];
    const float* w_hh = (const float*)d_in[8];
    const float* b_ih = (const float*)d_in[9];
    const float* b_hh = (const float*)d_in[10];
    const float* bn_g = (const float*)d_in[11];
    const float* bn_b = (const float*)d_in[12];
    const float* w10  = (const float*)d_in[13];
    const float* b10  = (const float*)d_in[14];
    const float* w11  = (const float*)d_in[15];
    const float* b11  = (const float*)d_in[16];
    const float* w12  = (const float*)d_in[17];
    const float* b12  = (const float*)d_in[18];
    float* out = (float*)d_out;

    frame_kernel<<<TT, 128>>>(x, w00, b00, w01, b01, ln_g, ln_b, w_ih, b_ih, b_hh);
    recur_kernel<<<1, 128>>>(w_hh, bn_g, bn_b, w10, b10, w11, b11, w12, b12, out);
}